// round 1
// baseline (speedup 1.0000x reference)
#include <cuda_runtime.h>
#include <math.h>

#define NN 50000
#define EE 400000
#define ETOT (EE + NN)   // with self loops
#define DD 256
#define HEADS 4
#define HIDC 64
#define GG 64
#define NEG_SLOPE 0.2f

// ---------------- static device scratch (no allocation allowed) ----------------
__device__ float g_h[NN * DD];       // feature buffer A
__device__ float g_o[NN * DD];       // feature buffer B
__device__ float g_asrc[NN * HEADS];
__device__ float g_adst[NN * HEADS];
__device__ int   g_deg[NN];
__device__ int   g_rowptr[NN + 1];
__device__ int   g_cursor[NN];
__device__ int   g_csrsrc[ETOT];
__device__ int   g_gcnt[GG];
__device__ int   g_gstart[GG + 1];
__device__ float g_pooled[GG * DD];

// ---------------- CSR build ----------------
__global__ void k_zero_counts() {
    int i = blockIdx.x * blockDim.x + threadIdx.x;
    if (i < NN) g_deg[i] = 0;
    if (i < GG) g_gcnt[i] = 0;
}

__global__ void k_hist_edges(const int* __restrict__ ei) {
    int i = blockIdx.x * blockDim.x + threadIdx.x;
    if (i < EE) {
        atomicAdd(&g_deg[ei[EE + i]], 1);   // dst row of edge_index
    } else if (i < ETOT) {
        atomicAdd(&g_deg[i - EE], 1);       // self loop
    }
}

// single-block exclusive scan of g_deg -> g_rowptr (N=50000)
__global__ void k_scan_deg() {
    __shared__ int sh[1024];
    __shared__ int carry_s;
    if (threadIdx.x == 0) carry_s = 0;
    __syncthreads();
    for (int base = 0; base < NN; base += 1024) {
        int i = base + (int)threadIdx.x;
        int v = (i < NN) ? g_deg[i] : 0;
        sh[threadIdx.x] = v;
        __syncthreads();
        #pragma unroll
        for (int off = 1; off < 1024; off <<= 1) {
            int t = (threadIdx.x >= off) ? sh[threadIdx.x - off] : 0;
            __syncthreads();
            sh[threadIdx.x] += t;
            __syncthreads();
        }
        int c = carry_s;
        if (i < NN) {
            g_rowptr[i] = c + sh[threadIdx.x] - v;  // exclusive
            g_cursor[i] = c + sh[threadIdx.x] - v;
        }
        __syncthreads();
        if (threadIdx.x == 1023) carry_s = c + sh[1023];
        __syncthreads();
    }
    if (threadIdx.x == 0) g_rowptr[NN] = carry_s;
}

__global__ void k_scatter_edges(const int* __restrict__ ei) {
    int i = blockIdx.x * blockDim.x + threadIdx.x;
    int src, dst;
    if (i < EE)          { src = ei[i]; dst = ei[EE + i]; }
    else if (i < ETOT)   { src = i - EE; dst = i - EE; }
    else return;
    int pos = atomicAdd(&g_cursor[dst], 1);
    g_csrsrc[pos] = src;
}

// ---------------- batch ranges for pooling ----------------
__global__ void k_hist_batch(const int* __restrict__ batch) {
    int i = blockIdx.x * blockDim.x + threadIdx.x;
    if (i < NN) atomicAdd(&g_gcnt[batch[i]], 1);
}

__global__ void k_scan_batch() {
    if (threadIdx.x == 0 && blockIdx.x == 0) {
        int c = 0;
        for (int g = 0; g < GG; g++) { g_gstart[g] = c; c += g_gcnt[g]; }
        g_gstart[GG] = c;
    }
}

// ---------------- SGEMM: C[M,256] = A[M,256] @ B[256,256] ----------------
#define BM 128
#define BN 64
#define BK 16
__global__ void __launch_bounds__(256) k_sgemm(const float* __restrict__ A,
                                               const float* __restrict__ B,
                                               float* __restrict__ C, int M) {
    __shared__ float As[BK][BM];
    __shared__ float Bs[BK][BN];
    const int tid = threadIdx.x;
    const int row0 = blockIdx.x * BM;
    const int col0 = blockIdx.y * BN;
    const int tm = tid >> 4;   // 0..15 -> 8 rows each
    const int tn = tid & 15;   // 0..15 -> 4 cols each

    float acc[8][4];
    #pragma unroll
    for (int i = 0; i < 8; i++)
        #pragma unroll
        for (int j = 0; j < 4; j++) acc[i][j] = 0.0f;

    for (int k0 = 0; k0 < 256; k0 += BK) {
        // load A tile: 128x16 floats, transposed into As[k][m]
        #pragma unroll
        for (int it = 0; it < 2; it++) {
            int id = tid + it * 256;      // 0..511 float4 slots
            int r = id >> 2;              // 0..127
            int c4 = (id & 3) * 4;        // 0,4,8,12
            int grow = row0 + r;
            float4 v = make_float4(0.f, 0.f, 0.f, 0.f);
            if (grow < M) v = *(const float4*)(A + (size_t)grow * 256 + k0 + c4);
            As[c4 + 0][r] = v.x; As[c4 + 1][r] = v.y;
            As[c4 + 2][r] = v.z; As[c4 + 3][r] = v.w;
        }
        // load B tile: 16x64 floats
        {
            int r = tid >> 4;            // 0..15
            int c4 = (tid & 15) * 4;     // 0..60
            float4 v = *(const float4*)(B + (size_t)(k0 + r) * 256 + col0 + c4);
            *(float4*)&Bs[r][c4] = v;
        }
        __syncthreads();
        #pragma unroll
        for (int k = 0; k < BK; k++) {
            float4 a0 = *(float4*)&As[k][tm * 8];
            float4 a1 = *(float4*)&As[k][tm * 8 + 4];
            float4 b  = *(float4*)&Bs[k][tn * 4];
            float av[8] = {a0.x, a0.y, a0.z, a0.w, a1.x, a1.y, a1.z, a1.w};
            float bv[4] = {b.x, b.y, b.z, b.w};
            #pragma unroll
            for (int i = 0; i < 8; i++)
                #pragma unroll
                for (int j = 0; j < 4; j++)
                    acc[i][j] = fmaf(av[i], bv[j], acc[i][j]);
        }
        __syncthreads();
    }
    #pragma unroll
    for (int i = 0; i < 8; i++) {
        int grow = row0 + tm * 8 + i;
        if (grow < M) {
            float4 v = make_float4(acc[i][0], acc[i][1], acc[i][2], acc[i][3]);
            *(float4*)(C + (size_t)grow * 256 + col0 + tn * 4) = v;
        }
    }
}

// ---------------- attention coefficients ----------------
__global__ void k_att(const float* __restrict__ h,
                      const float* __restrict__ as,
                      const float* __restrict__ ad) {
    int w = blockIdx.x * (blockDim.x >> 5) + (threadIdx.x >> 5);
    if (w >= NN * HEADS) return;
    int lane = threadIdx.x & 31;
    int n = w >> 2, t = w & 3;
    const float* r = h + (size_t)n * DD + t * HIDC;
    float h0 = r[lane], h1 = r[lane + 32];
    float s = h0 * as[t * HIDC + lane] + h1 * as[t * HIDC + 32 + lane];
    float d = h0 * ad[t * HIDC + lane] + h1 * ad[t * HIDC + 32 + lane];
    #pragma unroll
    for (int off = 16; off > 0; off >>= 1) {
        s += __shfl_xor_sync(0xffffffff, s, off);
        d += __shfl_xor_sync(0xffffffff, d, off);
    }
    if (lane == 0) { g_asrc[n * HEADS + t] = s; g_adst[n * HEADS + t] = d; }
}

// ---------------- GAT aggregation: warp per (dst node, head) ----------------
__global__ void k_aggregate(const float* __restrict__ h,
                            const float* __restrict__ bias,
                            float* __restrict__ out) {
    int w = blockIdx.x * (blockDim.x >> 5) + (threadIdx.x >> 5);
    if (w >= NN * HEADS) return;
    int lane = threadIdx.x & 31;
    int n = w >> 2, t = w & 3;
    int beg = g_rowptr[n], end = g_rowptr[n + 1];
    float adst = g_adst[n * HEADS + t];

    // pass 1: max over edges (lane-parallel)
    float m = -3.0e38f;
    for (int k = beg + lane; k < end; k += 32) {
        int s = g_csrsrc[k];
        float e = g_asrc[s * HEADS + t] + adst;
        e = (e > 0.f) ? e : NEG_SLOPE * e;
        m = fmaxf(m, e);
    }
    #pragma unroll
    for (int off = 16; off > 0; off >>= 1)
        m = fmaxf(m, __shfl_xor_sync(0xffffffff, m, off));

    // pass 2: weighted accumulation (edge-serial, channel-parallel)
    float acc0 = 0.f, acc1 = 0.f, denom = 0.f;
    const float* hb = h + t * HIDC;
    for (int k = beg; k < end; k++) {
        int s = g_csrsrc[k];
        float e = g_asrc[s * HEADS + t] + adst;
        e = (e > 0.f) ? e : NEG_SLOPE * e;
        float wgt = __expf(e - m);
        denom += wgt;
        const float* row = hb + (size_t)s * DD;
        acc0 = fmaf(wgt, row[lane], acc0);
        acc1 = fmaf(wgt, row[lane + 32], acc1);
    }
    float inv = 1.0f / denom;
    int o = n * DD + t * HIDC + lane;
    out[o]      = acc0 * inv + bias[t * HIDC + lane];
    out[o + 32] = acc1 * inv + bias[t * HIDC + 32 + lane];
}

// ---------------- LayerNorm + ReLU (warp per row, safe in-place) ----------------
__global__ void k_ln_relu(const float* __restrict__ in,
                          const float* __restrict__ gamma,
                          const float* __restrict__ beta,
                          float* __restrict__ out) {
    int w = blockIdx.x * (blockDim.x >> 5) + (threadIdx.x >> 5);
    if (w >= NN) return;
    int lane = threadIdx.x & 31;
    const float* r = in + (size_t)w * DD;
    float v[8];
    float s = 0.f;
    #pragma unroll
    for (int i = 0; i < 8; i++) { v[i] = r[lane + 32 * i]; s += v[i]; }
    #pragma unroll
    for (int off = 16; off > 0; off >>= 1) s += __shfl_xor_sync(0xffffffff, s, off);
    float mu = s * (1.0f / 256.0f);
    float q = 0.f;
    #pragma unroll
    for (int i = 0; i < 8; i++) { float d = v[i] - mu; q = fmaf(d, d, q); }
    #pragma unroll
    for (int off = 16; off > 0; off >>= 1) q += __shfl_xor_sync(0xffffffff, q, off);
    float inv = rsqrtf(q * (1.0f / 256.0f) + 1e-5f);
    #pragma unroll
    for (int i = 0; i < 8; i++) {
        int c = lane + 32 * i;
        float y = (v[i] - mu) * inv * gamma[c] + beta[c];
        out[(size_t)w * DD + c] = fmaxf(y, 0.f);
    }
}

// ---------------- global mean pool ----------------
__global__ void k_pool(const float* __restrict__ h) {
    int g = blockIdx.x;
    int col = blockIdx.y * 128 + threadIdx.x;
    int s = g_gstart[g], e = g_gstart[g + 1];
    float sum = 0.f;
    for (int i = s; i < e; i++) sum += h[(size_t)i * DD + col];
    int cnt = e - s;
    g_pooled[g * DD + col] = sum / (float)max(cnt, 1);
}

// ---------------- final MLP ----------------
__global__ void k_mlp(const float* __restrict__ lw1, const float* __restrict__ lb1,
                      const float* __restrict__ lw2, const float* __restrict__ lb2,
                      float* __restrict__ out) {
    __shared__ float p[DD];
    __shared__ float hid[HIDC];
    int g = blockIdx.x, tid = threadIdx.x;  // 64 threads
    for (int i = tid; i < DD; i += 64) p[i] = g_pooled[g * DD + i];
    __syncthreads();
    float s = lb1[tid];
    #pragma unroll 8
    for (int k = 0; k < DD; k++) s = fmaf(p[k], lw1[k * HIDC + tid], s);
    hid[tid] = fmaxf(s, 0.f);
    __syncthreads();
    if (tid < 2) {
        float o = lb2[tid];
        #pragma unroll
        for (int k = 0; k < HIDC; k++) o = fmaf(hid[k], lw2[k * 2 + tid], o);
        out[g * 2 + tid] = o;
    }
}

// ---------------- host launcher ----------------
extern "C" void kernel_launch(void* const* d_in, const int* in_sizes, int n_in,
                              void* d_out, int out_size) {
    const float* x   = (const float*)d_in[0];
    const int*   ei  = (const int*)d_in[1];
    const int*   bat = (const int*)d_in[2];
    const float* W1  = (const float*)d_in[3];
    const float* as1 = (const float*)d_in[4];
    const float* ad1 = (const float*)d_in[5];
    const float* b1  = (const float*)d_in[6];
    const float* g1  = (const float*)d_in[7];
    const float* be1 = (const float*)d_in[8];
    const float* W2  = (const float*)d_in[9];
    const float* as2 = (const float*)d_in[10];
    const float* ad2 = (const float*)d_in[11];
    const float* b2  = (const float*)d_in[12];
    const float* g2  = (const float*)d_in[13];
    const float* be2 = (const float*)d_in[14];
    const float* lw1 = (const float*)d_in[15];
    const float* lb1 = (const float*)d_in[16];
    const float* lw2 = (const float*)d_in[17];
    const float* lb2 = (const float*)d_in[18];
    float* out = (float*)d_out;

    float *bh, *bo;
    cudaGetSymbolAddress((void**)&bh, g_h);
    cudaGetSymbolAddress((void**)&bo, g_o);

    // CSR + batch ranges
    k_zero_counts<<<(NN + 255) / 256, 256>>>();
    k_hist_edges<<<(ETOT + 255) / 256, 256>>>(ei);
    k_hist_batch<<<(NN + 255) / 256, 256>>>(bat);
    k_scan_deg<<<1, 1024>>>();
    k_scatter_edges<<<(ETOT + 255) / 256, 256>>>(ei);
    k_scan_batch<<<1, 32>>>();

    dim3 gemm_grid((NN + BM - 1) / BM, 256 / BN);
    int warp_blocks = (NN * HEADS + 7) / 8;       // 8 warps / 256-thread block
    int ln_blocks   = (NN + 7) / 8;

    // ---- layer 1 ----
    k_sgemm<<<gemm_grid, 256>>>(x, W1, bh, NN);
    k_att<<<warp_blocks, 256>>>(bh, as1, ad1);
    k_aggregate<<<warp_blocks, 256>>>(bh, b1, bo);
    k_ln_relu<<<ln_blocks, 256>>>(bo, g1, be1, bh);

    // ---- layer 2 ----
    k_sgemm<<<gemm_grid, 256>>>(bh, W2, bo, NN);
    k_att<<<warp_blocks, 256>>>(bo, as2, ad2);
    k_aggregate<<<warp_blocks, 256>>>(bo, b2, bh);
    k_ln_relu<<<ln_blocks, 256>>>(bh, g2, be2, bh);

    // ---- pool + MLP ----
    k_pool<<<dim3(GG, 2), 128>>>(bh);
    k_mlp<<<GG, 64>>>(lw1, lb1, lw2, lb2, out);
}

// round 3
// speedup vs baseline: 1.2544x; 1.2544x over previous
#include <cuda_runtime.h>
#include <cuda_bf16.h>
#include <cstdint>
#include <math.h>

#define NN 50000
#define EE 400000
#define ETOT (EE + NN)
#define DD 256
#define HEADS 4
#define HIDC 64
#define GG 64
#define NEG_SLOPE 0.2f

// ---------------- static device scratch ----------------
__device__ float g_h[NN * DD];          // GEMM output (pre-aggregation features)
__device__ float g_o[NN * DD];          // post agg+LN features
__device__ __nv_bfloat16 g_ahi[NN * DD];
__device__ __nv_bfloat16 g_alo[NN * DD];
__device__ __nv_bfloat16 g_w1hi[DD * DD], g_w1lo[DD * DD];
__device__ __nv_bfloat16 g_w2hi[DD * DD], g_w2lo[DD * DD];
__device__ float g_asrc[NN * HEADS];
__device__ float g_adst[NN * HEADS];
__device__ int   g_deg[NN];
__device__ int   g_rowptr[NN + 1];
__device__ int   g_cursor[NN];
__device__ int   g_csrsrc[ETOT];
__device__ int   g_gcnt[GG];
__device__ int   g_gstart[GG + 1];
__device__ float g_pooled[GG * DD];
#define SNB 98
__device__ int   g_bsum[SNB];
__device__ int   g_boff[SNB];

// ---------------- helpers ----------------
__device__ __forceinline__ uint32_t su32(const void* p) {
    uint32_t a;
    asm("{ .reg .u64 t; cvta.to.shared.u64 t, %1; cvt.u32.u64 %0, t; }" : "=r"(a) : "l"(p));
    return a;
}
__device__ __forceinline__ uint32_t swz(uint32_t off) {    // SW128-style xor swizzle
    return off ^ ((off >> 3) & 0x70);
}
__device__ __forceinline__ void ldsm_x4(uint32_t* r, uint32_t addr) {
    asm volatile("ldmatrix.sync.aligned.m8n8.x4.shared.b16 {%0,%1,%2,%3}, [%4];"
                 : "=r"(r[0]), "=r"(r[1]), "=r"(r[2]), "=r"(r[3]) : "r"(addr));
}
__device__ __forceinline__ void mma_bf16(float* c, const uint32_t* a, const uint32_t* b) {
    asm volatile("mma.sync.aligned.m16n8k16.row.col.f32.bf16.bf16.f32 "
                 "{%0,%1,%2,%3}, {%4,%5,%6,%7}, {%8,%9}, {%0,%1,%2,%3};"
                 : "+f"(c[0]), "+f"(c[1]), "+f"(c[2]), "+f"(c[3])
                 : "r"(a[0]), "r"(a[1]), "r"(a[2]), "r"(a[3]), "r"(b[0]), "r"(b[1]));
}

// ---------------- CSR build ----------------
__global__ void k_zero_counts() {
    int i = blockIdx.x * blockDim.x + threadIdx.x;
    if (i < NN) g_deg[i] = 0;
    if (i < GG) g_gcnt[i] = 0;
}
__global__ void k_hist_edges(const int* __restrict__ ei) {
    int i = blockIdx.x * blockDim.x + threadIdx.x;
    if (i < EE) atomicAdd(&g_deg[ei[EE + i]], 1);
    else if (i < ETOT) atomicAdd(&g_deg[i - EE], 1);
}
__global__ void k_scan_part() {
    __shared__ int sh[512];
    int i = blockIdx.x * 512 + threadIdx.x;
    int v = (i < NN) ? g_deg[i] : 0;
    sh[threadIdx.x] = v;
    __syncthreads();
    #pragma unroll
    for (int off = 1; off < 512; off <<= 1) {
        int t = (threadIdx.x >= off) ? sh[threadIdx.x - off] : 0;
        __syncthreads();
        sh[threadIdx.x] += t;
        __syncthreads();
    }
    if (i < NN) g_rowptr[i] = sh[threadIdx.x] - v;
    if (threadIdx.x == 511) g_bsum[blockIdx.x] = sh[511];
}
__global__ void k_scan_boff() {
    int c = 0;
    for (int b = 0; b < SNB; b++) { g_boff[b] = c; c += g_bsum[b]; }
}
__global__ void k_scan_add() {
    int i = blockIdx.x * blockDim.x + threadIdx.x;
    if (i < NN) {
        int val = g_rowptr[i] + g_boff[i >> 9];
        g_rowptr[i] = val;
        g_cursor[i] = val;
    }
    if (i == 0) g_rowptr[NN] = ETOT;
}
__global__ void k_scatter_edges(const int* __restrict__ ei) {
    int i = blockIdx.x * blockDim.x + threadIdx.x;
    int src, dst;
    if (i < EE)        { src = ei[i]; dst = ei[EE + i]; }
    else if (i < ETOT) { src = i - EE; dst = i - EE; }
    else return;
    int pos = atomicAdd(&g_cursor[dst], 1);
    g_csrsrc[pos] = src;
}
__global__ void k_hist_batch(const int* __restrict__ batch) {
    int i = blockIdx.x * blockDim.x + threadIdx.x;
    if (i < NN) atomicAdd(&g_gcnt[batch[i]], 1);
}
__global__ void k_scan_batch() {
    int c = 0;
    for (int g = 0; g < GG; g++) { g_gstart[g] = c; c += g_gcnt[g]; }
    g_gstart[GG] = c;
}

// ---------------- fp32 -> bf16 hi/lo splits ----------------
__global__ void k_split_x(const float* __restrict__ x,
                          __nv_bfloat16* __restrict__ hi, __nv_bfloat16* __restrict__ lo) {
    int i = blockIdx.x * 256 + threadIdx.x;
    float v = x[i];
    __nv_bfloat16 h = __float2bfloat16(v);
    hi[i] = h;
    lo[i] = __float2bfloat16(v - __bfloat162float(h));
}
// W[k][n] -> Wt[n][k] split (K-major rows -> mma row.col "B col-major")
__global__ void k_split_wt(const float* __restrict__ W,
                           __nv_bfloat16* __restrict__ hi, __nv_bfloat16* __restrict__ lo) {
    int i = blockIdx.x * 256 + threadIdx.x;   // 65536
    int n = i >> 8, k = i & 255;
    float v = W[k * 256 + n];
    __nv_bfloat16 h = __float2bfloat16(v);
    hi[i] = h;
    lo[i] = __float2bfloat16(v - __bfloat162float(h));
}

// ---------------- mma.sync bf16 GEMM: C[M,256] = A[M,256] @ Wt^T ----------------
// 3-pass split product: hi*hi + hi*lo + lo*hi, fp32 accumulation.
#define SA_HI 0
#define SA_LO 16384
#define SB_HI 32768
#define SB_LO 49152
#define SMEM_TOT 65536

__global__ void __launch_bounds__(256) k_mmagemm(
    const __nv_bfloat16* __restrict__ Ahi, const __nv_bfloat16* __restrict__ Alo,
    const __nv_bfloat16* __restrict__ Bhi, const __nv_bfloat16* __restrict__ Blo,
    float* __restrict__ C, int M)
{
    extern __shared__ char smem[];
    uint32_t sb = su32(smem);
    const int tid = threadIdx.x, wid = tid >> 5, lane = tid & 31;
    const int row0 = blockIdx.x * 128;
    const int col0 = blockIdx.y * 128;
    const int wm = wid & 3;       // warp row group: 32 rows
    const int wn = wid >> 2;      // warp col group: 64 cols

    float acc[2][8][4];
    #pragma unroll
    for (int a = 0; a < 2; a++)
        #pragma unroll
        for (int b = 0; b < 8; b++)
            #pragma unroll
            for (int q = 0; q < 4; q++) acc[a][b][q] = 0.f;

    // per-lane ldmatrix address components for A (within 128-row x 64-col chunk)
    const int lrow = lane & 15;
    const int lcol = (lane >> 4) * 8;

    for (int c = 0; c < 4; c++) {
        // ---- global -> smem (A chunk 128x64, B chunk 128x64, hi+lo) ----
        #pragma unroll
        for (int it = 0; it < 4; it++) {
            int u = tid + it * 256;          // 1024 int4 slots
            int r = u >> 3, j = u & 7;
            uint32_t sw = swz(r * 128 + j * 16);
            int m = row0 + r;
            int4 vh, vl;
            if (m < M) {
                size_t gi = (size_t)m * 256 + c * 64 + j * 8;
                vh = *(const int4*)(Ahi + gi);
                vl = *(const int4*)(Alo + gi);
            } else { vh = make_int4(0, 0, 0, 0); vl = vh; }
            *(int4*)(smem + SA_HI + sw) = vh;
            *(int4*)(smem + SA_LO + sw) = vl;
            size_t bi = (size_t)(col0 + r) * 256 + c * 64 + j * 8;
            *(int4*)(smem + SB_HI + sw) = *(const int4*)(Bhi + bi);
            *(int4*)(smem + SB_LO + sw) = *(const int4*)(Blo + bi);
        }
        __syncthreads();

        // ---- compute ----
        #pragma unroll
        for (int kk = 0; kk < 4; kk++) {
            uint32_t ah[2][4], al[2][4];
            #pragma unroll
            for (int mt = 0; mt < 2; mt++) {
                uint32_t off = swz((wm * 32 + mt * 16 + lrow) * 128 + (kk * 16 + lcol) * 2);
                ldsm_x4(ah[mt], sb + SA_HI + off);
                ldsm_x4(al[mt], sb + SA_LO + off);
            }
            #pragma unroll
            for (int nt = 0; nt < 8; nt++) {
                int nrow = wn * 64 + nt * 8 + (lane >> 2);
                int k0 = kk * 16 + (lane & 3) * 2;
                uint32_t o0 = swz(nrow * 128 + k0 * 2);
                uint32_t o1 = swz(nrow * 128 + (k0 + 8) * 2);
                uint32_t bh[2], bl[2];
                bh[0] = *(const uint32_t*)(smem + SB_HI + o0);
                bh[1] = *(const uint32_t*)(smem + SB_HI + o1);
                bl[0] = *(const uint32_t*)(smem + SB_LO + o0);
                bl[1] = *(const uint32_t*)(smem + SB_LO + o1);
                #pragma unroll
                for (int mt = 0; mt < 2; mt++) {
                    mma_bf16(acc[mt][nt], ah[mt], bh);
                    mma_bf16(acc[mt][nt], ah[mt], bl);
                    mma_bf16(acc[mt][nt], al[mt], bh);
                }
            }
        }
        __syncthreads();
    }

    // ---- epilogue: fragment -> C ----
    #pragma unroll
    for (int mt = 0; mt < 2; mt++) {
        int r0 = row0 + wm * 32 + mt * 16 + (lane >> 2);
        int r1 = r0 + 8;
        #pragma unroll
        for (int nt = 0; nt < 8; nt++) {
            int cc = col0 + wn * 64 + nt * 8 + (lane & 3) * 2;
            if (r0 < M) *(float2*)(C + (size_t)r0 * 256 + cc) = make_float2(acc[mt][nt][0], acc[mt][nt][1]);
            if (r1 < M) *(float2*)(C + (size_t)r1 * 256 + cc) = make_float2(acc[mt][nt][2], acc[mt][nt][3]);
        }
    }
}

// ---------------- attention coefficients ----------------
__global__ void k_att(const float* __restrict__ h,
                      const float* __restrict__ as,
                      const float* __restrict__ ad) {
    int w = blockIdx.x * (blockDim.x >> 5) + (threadIdx.x >> 5);
    if (w >= NN * HEADS) return;
    int lane = threadIdx.x & 31;
    int n = w >> 2, t = w & 3;
    const float* r = h + (size_t)n * DD + t * HIDC;
    float h0 = r[lane], h1 = r[lane + 32];
    float s = h0 * as[t * HIDC + lane] + h1 * as[t * HIDC + 32 + lane];
    float d = h0 * ad[t * HIDC + lane] + h1 * ad[t * HIDC + 32 + lane];
    #pragma unroll
    for (int off = 16; off > 0; off >>= 1) {
        s += __shfl_xor_sync(0xffffffff, s, off);
        d += __shfl_xor_sync(0xffffffff, d, off);
    }
    if (lane == 0) { g_asrc[n * HEADS + t] = s; g_adst[n * HEADS + t] = d; }
}

// ---------------- fused GAT aggregation + bias + LayerNorm + ReLU + bf16-split ----------------
__global__ void __launch_bounds__(128) k_agg_ln(
    const float* __restrict__ h, const float* __restrict__ bias,
    const float* __restrict__ gamma, const float* __restrict__ beta,
    float* __restrict__ outf, __nv_bfloat16* __restrict__ ohi, __nv_bfloat16* __restrict__ olo)
{
    int n = blockIdx.x;
    int t = threadIdx.x >> 5, lane = threadIdx.x & 31;
    __shared__ float sh[DD];
    __shared__ float red[8];
    int beg = g_rowptr[n], end = g_rowptr[n + 1];
    float adst = g_adst[n * HEADS + t];

    float m = -3.0e38f;
    for (int k = beg + lane; k < end; k += 32) {
        float e = g_asrc[g_csrsrc[k] * HEADS + t] + adst;
        e = (e > 0.f) ? e : NEG_SLOPE * e;
        m = fmaxf(m, e);
    }
    #pragma unroll
    for (int off = 16; off > 0; off >>= 1)
        m = fmaxf(m, __shfl_xor_sync(0xffffffff, m, off));

    float acc0 = 0.f, acc1 = 0.f, den = 0.f;
    const float* hb = h + t * HIDC;
    for (int k = beg; k < end; k++) {
        int s = g_csrsrc[k];
        float e = g_asrc[s * HEADS + t] + adst;
        e = (e > 0.f) ? e : NEG_SLOPE * e;
        float w = __expf(e - m);
        den += w;
        const float* row = hb + (size_t)s * DD;
        acc0 = fmaf(w, row[lane], acc0);
        acc1 = fmaf(w, row[lane + 32], acc1);
    }
    float inv = 1.0f / den;
    sh[t * HIDC + lane] = acc0 * inv + bias[t * HIDC + lane];
    sh[t * HIDC + 32 + lane] = acc1 * inv + bias[t * HIDC + 32 + lane];
    __syncthreads();

    float v0 = sh[threadIdx.x], v1 = sh[128 + threadIdx.x];
    float s = v0 + v1;
    #pragma unroll
    for (int off = 16; off > 0; off >>= 1) s += __shfl_xor_sync(0xffffffff, s, off);
    if (lane == 0) red[t] = s;
    __syncthreads();
    float mu = (red[0] + red[1] + red[2] + red[3]) * (1.0f / 256.0f);
    float d0 = v0 - mu, d1 = v1 - mu;
    float q = d0 * d0 + d1 * d1;
    #pragma unroll
    for (int off = 16; off > 0; off >>= 1) q += __shfl_xor_sync(0xffffffff, q, off);
    if (lane == 0) red[4 + t] = q;
    __syncthreads();
    float invs = rsqrtf((red[4] + red[5] + red[6] + red[7]) * (1.0f / 256.0f) + 1e-5f);

    int c0 = threadIdx.x, c1 = 128 + threadIdx.x;
    float y0 = fmaxf(d0 * invs * gamma[c0] + beta[c0], 0.f);
    float y1 = fmaxf(d1 * invs * gamma[c1] + beta[c1], 0.f);
    size_t o = (size_t)n * DD;
    outf[o + c0] = y0;
    outf[o + c1] = y1;
    __nv_bfloat16 b0 = __float2bfloat16(y0);
    __nv_bfloat16 b1 = __float2bfloat16(y1);
    ohi[o + c0] = b0; olo[o + c0] = __float2bfloat16(y0 - __bfloat162float(b0));
    ohi[o + c1] = b1; olo[o + c1] = __float2bfloat16(y1 - __bfloat162float(b1));
}

// ---------------- global mean pool ----------------
__global__ void k_pool(const float* __restrict__ h) {
    int g = blockIdx.x;
    int col = blockIdx.y * 128 + threadIdx.x;
    int s = g_gstart[g], e = g_gstart[g + 1];
    float sum = 0.f;
    for (int i = s; i < e; i++) sum += h[(size_t)i * DD + col];
    int cnt = e - s;
    g_pooled[g * DD + col] = sum / (float)max(cnt, 1);
}

// ---------------- final MLP ----------------
__global__ void k_mlp(const float* __restrict__ lw1, const float* __restrict__ lb1,
                      const float* __restrict__ lw2, const float* __restrict__ lb2,
                      float* __restrict__ out) {
    __shared__ float p[DD];
    __shared__ float hid[HIDC];
    int g = blockIdx.x, tid = threadIdx.x;
    for (int i = tid; i < DD; i += 64) p[i] = g_pooled[g * DD + i];
    __syncthreads();
    float s = lb1[tid];
    #pragma unroll 8
    for (int k = 0; k < DD; k++) s = fmaf(p[k], lw1[k * HIDC + tid], s);
    hid[tid] = fmaxf(s, 0.f);
    __syncthreads();
    if (tid < 2) {
        float o = lb2[tid];
        #pragma unroll
        for (int k = 0; k < HIDC; k++) o = fmaf(hid[k], lw2[k * 2 + tid], o);
        out[g * 2 + tid] = o;
    }
}

// ---------------- host launcher ----------------
extern "C" void kernel_launch(void* const* d_in, const int* in_sizes, int n_in,
                              void* d_out, int out_size) {
    const float* x   = (const float*)d_in[0];
    const int*   ei  = (const int*)d_in[1];
    const int*   bat = (const int*)d_in[2];
    const float* W1  = (const float*)d_in[3];
    const float* as1 = (const float*)d_in[4];
    const float* ad1 = (const float*)d_in[5];
    const float* b1  = (const float*)d_in[6];
    const float* g1  = (const float*)d_in[7];
    const float* be1 = (const float*)d_in[8];
    const float* W2  = (const float*)d_in[9];
    const float* as2 = (const float*)d_in[10];
    const float* ad2 = (const float*)d_in[11];
    const float* b2  = (const float*)d_in[12];
    const float* g2  = (const float*)d_in[13];
    const float* be2 = (const float*)d_in[14];
    const float* lw1 = (const float*)d_in[15];
    const float* lb1 = (const float*)d_in[16];
    const float* lw2 = (const float*)d_in[17];
    const float* lb2 = (const float*)d_in[18];
    float* out = (float*)d_out;

    cudaFuncSetAttribute(k_mmagemm, cudaFuncAttributeMaxDynamicSharedMemorySize, SMEM_TOT);

    float *bh, *bo;
    __nv_bfloat16 *ahi, *alo, *w1h, *w1l, *w2h, *w2l;
    cudaGetSymbolAddress((void**)&bh, g_h);
    cudaGetSymbolAddress((void**)&bo, g_o);
    cudaGetSymbolAddress((void**)&ahi, g_ahi);
    cudaGetSymbolAddress((void**)&alo, g_alo);
    cudaGetSymbolAddress((void**)&w1h, g_w1hi);
    cudaGetSymbolAddress((void**)&w1l, g_w1lo);
    cudaGetSymbolAddress((void**)&w2h, g_w2hi);
    cudaGetSymbolAddress((void**)&w2l, g_w2lo);

    // CSR + batch ranges + splits
    k_zero_counts<<<(NN + 255) / 256, 256>>>();
    k_hist_edges<<<(ETOT + 255) / 256, 256>>>(ei);
    k_hist_batch<<<(NN + 255) / 256, 256>>>(bat);
    k_scan_part<<<SNB, 512>>>();
    k_scan_boff<<<1, 1>>>();
    k_scan_add<<<(NN + 255) / 256, 256>>>();
    k_scatter_edges<<<(ETOT + 255) / 256, 256>>>(ei);
    k_scan_batch<<<1, 1>>>();
    k_split_x<<<NN * DD / 256, 256>>>(x, ahi, alo);
    k_split_wt<<<DD * DD / 256, 256>>>(W1, w1h, w1l);
    k_split_wt<<<DD * DD / 256, 256>>>(W2, w2h, w2l);

    dim3 gemm_grid((NN + 127) / 128, 2);
    int warp_blocks = (NN * HEADS + 7) / 8;

    // ---- layer 1 ----
    k_mmagemm<<<gemm_grid, 256, SMEM_TOT>>>(ahi, alo, w1h, w1l, bh, NN);
    k_att<<<warp_blocks, 256>>>(bh, as1, ad1);
    k_agg_ln<<<NN, 128>>>(bh, b1, g1, be1, bo, ahi, alo);

    // ---- layer 2 ----
    k_mmagemm<<<gemm_grid, 256, SMEM_TOT>>>(ahi, alo, w2h, w2l, bh, NN);
    k_att<<<warp_blocks, 256>>>(bh, as2, ad2);
    k_agg_ln<<<NN, 128>>>(bh, b2, g2, be2, bo, ahi, alo);

    // ---- pool + MLP ----
    k_pool<<<dim3(GG, 2), 128>>>(bo);
    k_mlp<<<GG, 64>>>(lw1, lb1, lw2, lb2, out);
}

// round 4
// speedup vs baseline: 1.6322x; 1.3012x over previous
#include <cuda_runtime.h>
#include <cuda_bf16.h>
#include <cstdint>
#include <math.h>

#define NN 50000
#define EE 400000
#define ETOT (EE + NN)
#define DD 256
#define HEADS 4
#define HIDC 64
#define GG 64
#define NEG_SLOPE 0.2f

// ---------------- static device scratch ----------------
__device__ float g_h[NN * DD];
__device__ float g_o[NN * DD];
__device__ __nv_bfloat16 g_ahi[NN * DD];
__device__ __nv_bfloat16 g_alo[NN * DD];
__device__ __nv_bfloat16 g_w1hi[DD * DD], g_w1lo[DD * DD];
__device__ __nv_bfloat16 g_w2hi[DD * DD], g_w2lo[DD * DD];
__device__ float g_asrc[NN * HEADS];
__device__ float g_adst[NN * HEADS];
__device__ int   g_deg[NN];
__device__ int   g_rowptr[NN + 1];
__device__ int   g_cursor[NN];
__device__ int   g_csrsrc[ETOT];
__device__ int   g_gcnt[GG];
__device__ int   g_gstart[GG + 1];
__device__ float g_pooled[GG * DD];
#define SNB 98
__device__ int   g_bsum[SNB];
__device__ int   g_boff[SNB];

// ---------------- helpers ----------------
__device__ __forceinline__ uint32_t su32(const void* p) {
    uint32_t a;
    asm("{ .reg .u64 t; cvta.to.shared.u64 t, %1; cvt.u32.u64 %0, t; }" : "=r"(a) : "l"(p));
    return a;
}
__device__ __forceinline__ uint32_t swz(uint32_t off) {
    return off ^ ((off >> 3) & 0x70);
}
__device__ __forceinline__ void ldsm_x4(uint32_t* r, uint32_t addr) {
    asm volatile("ldmatrix.sync.aligned.m8n8.x4.shared.b16 {%0,%1,%2,%3}, [%4];"
                 : "=r"(r[0]), "=r"(r[1]), "=r"(r[2]), "=r"(r[3]) : "r"(addr));
}
__device__ __forceinline__ void mma_bf16(float* c, const uint32_t* a, const uint32_t* b) {
    asm volatile("mma.sync.aligned.m16n8k16.row.col.f32.bf16.bf16.f32 "
                 "{%0,%1,%2,%3}, {%4,%5,%6,%7}, {%8,%9}, {%0,%1,%2,%3};"
                 : "+f"(c[0]), "+f"(c[1]), "+f"(c[2]), "+f"(c[3])
                 : "r"(a[0]), "r"(a[1]), "r"(a[2]), "r"(a[3]), "r"(b[0]), "r"(b[1]));
}
__device__ __forceinline__ void cp16(uint32_t dst, const void* src, uint32_t sz) {
    asm volatile("cp.async.cg.shared.global [%0], [%1], 16, %2;" :: "r"(dst), "l"(src), "r"(sz));
}
__device__ __forceinline__ void cp16f(uint32_t dst, const void* src) {
    asm volatile("cp.async.cg.shared.global [%0], [%1], 16;" :: "r"(dst), "l"(src));
}
#define CP_COMMIT() asm volatile("cp.async.commit_group;" ::: "memory")
#define CP_WAIT(n)  asm volatile("cp.async.wait_group %0;" :: "n"(n) : "memory")

// ---------------- CSR build ----------------
__global__ void k_zero_counts() {
    int i = blockIdx.x * blockDim.x + threadIdx.x;
    if (i < NN) g_deg[i] = 0;
    if (i < GG) g_gcnt[i] = 0;
}
__global__ void k_hist_edges(const int* __restrict__ ei) {
    int i = blockIdx.x * blockDim.x + threadIdx.x;
    if (i < EE) atomicAdd(&g_deg[ei[EE + i]], 1);
    else if (i < ETOT) atomicAdd(&g_deg[i - EE], 1);
}
__global__ void k_scan_part() {
    __shared__ int sh[512];
    int i = blockIdx.x * 512 + threadIdx.x;
    int v = (i < NN) ? g_deg[i] : 0;
    sh[threadIdx.x] = v;
    __syncthreads();
    #pragma unroll
    for (int off = 1; off < 512; off <<= 1) {
        int t = (threadIdx.x >= off) ? sh[threadIdx.x - off] : 0;
        __syncthreads();
        sh[threadIdx.x] += t;
        __syncthreads();
    }
    if (i < NN) g_rowptr[i] = sh[threadIdx.x] - v;
    if (threadIdx.x == 511) g_bsum[blockIdx.x] = sh[511];
}
__global__ void k_scan_boff() {
    int c = 0;
    for (int b = 0; b < SNB; b++) { g_boff[b] = c; c += g_bsum[b]; }
}
__global__ void k_scan_add() {
    int i = blockIdx.x * blockDim.x + threadIdx.x;
    if (i < NN) {
        int val = g_rowptr[i] + g_boff[i >> 9];
        g_rowptr[i] = val;
        g_cursor[i] = val;
    }
    if (i == 0) g_rowptr[NN] = ETOT;
}
__global__ void k_scatter_edges(const int* __restrict__ ei) {
    int i = blockIdx.x * blockDim.x + threadIdx.x;
    int src, dst;
    if (i < EE)        { src = ei[i]; dst = ei[EE + i]; }
    else if (i < ETOT) { src = i - EE; dst = i - EE; }
    else return;
    int pos = atomicAdd(&g_cursor[dst], 1);
    g_csrsrc[pos] = src;
}
__global__ void k_hist_batch(const int* __restrict__ batch) {
    int i = blockIdx.x * blockDim.x + threadIdx.x;
    if (i < NN) atomicAdd(&g_gcnt[batch[i]], 1);
}
__global__ void k_scan_batch() {
    int c = 0;
    for (int g = 0; g < GG; g++) { g_gstart[g] = c; c += g_gcnt[g]; }
    g_gstart[GG] = c;
}

// ---------------- fp32 -> bf16 hi/lo splits ----------------
__global__ void k_split_x(const float* __restrict__ x,
                          __nv_bfloat16* __restrict__ hi, __nv_bfloat16* __restrict__ lo) {
    int i = blockIdx.x * 256 + threadIdx.x;
    float v = x[i];
    __nv_bfloat16 h = __float2bfloat16(v);
    hi[i] = h;
    lo[i] = __float2bfloat16(v - __bfloat162float(h));
}
__global__ void k_split_wt(const float* __restrict__ W,
                           __nv_bfloat16* __restrict__ hi, __nv_bfloat16* __restrict__ lo) {
    int i = blockIdx.x * 256 + threadIdx.x;
    int n = i >> 8, k = i & 255;
    float v = W[k * 256 + n];
    __nv_bfloat16 h = __float2bfloat16(v);
    hi[i] = h;
    lo[i] = __float2bfloat16(v - __bfloat162float(h));
}

// ---------------- GEMM: C[M,256] = A @ Wt^T, fused att-coef epilogue ----------------
// stage layout (per 64-K chunk): A hi 16K, A lo 16K, B hi 32K, B lo 32K = 96KB, x2 stages
#define STG   98304
#define OA_HI 0
#define OA_LO 16384
#define OB_HI 32768
#define OB_LO 65536
#define SMEM_TOT (2 * STG)

__global__ void __launch_bounds__(256) k_mmagemm(
    const __nv_bfloat16* __restrict__ Ahi, const __nv_bfloat16* __restrict__ Alo,
    const __nv_bfloat16* __restrict__ Bhi, const __nv_bfloat16* __restrict__ Blo,
    float* __restrict__ C,
    const float* __restrict__ attس_unused, // placeholder removed below
    int M);

__global__ void __launch_bounds__(256) k_gemm_att(
    const __nv_bfloat16* __restrict__ Ahi, const __nv_bfloat16* __restrict__ Alo,
    const __nv_bfloat16* __restrict__ Bhi, const __nv_bfloat16* __restrict__ Blo,
    float* __restrict__ C,
    const float* __restrict__ as, const float* __restrict__ ad,
    int M)
{
    extern __shared__ char smem[];
    uint32_t sb = su32(smem);
    const int tid = threadIdx.x, wid = tid >> 5, lane = tid & 31;
    const int row0 = blockIdx.x * 128;
    const int wm = wid & 3;       // 4 row groups of 32
    const int wn = wid >> 2;      // 2 col groups of 128

    float acc[2][16][4];
    #pragma unroll
    for (int a = 0; a < 2; a++)
        #pragma unroll
        for (int b = 0; b < 16; b++)
            #pragma unroll
            for (int q = 0; q < 4; q++) acc[a][b][q] = 0.f;

    // ---- async chunk loader ----
    auto load_chunk = [&](int c, int stage) {
        uint32_t base = sb + stage * STG;
        #pragma unroll
        for (int it = 0; it < 4; it++) {          // A: 1024 16B slots
            int u = tid + it * 256;
            int r = u >> 3, j = u & 7;
            uint32_t sw = swz(r * 128 + j * 16);
            int m = row0 + r;
            int mc = m < M ? m : (M - 1);
            uint32_t sz = (m < M) ? 16u : 0u;
            size_t gi = (size_t)mc * 256 + c * 64 + j * 8;
            cp16(base + OA_HI + sw, Ahi + gi, sz);
            cp16(base + OA_LO + sw, Alo + gi, sz);
        }
        #pragma unroll
        for (int it = 0; it < 8; it++) {          // B: 2048 16B slots (256 rows)
            int u = tid + it * 256;
            int r = u >> 3, j = u & 7;
            uint32_t sw = swz(r * 128 + j * 16);
            size_t gi = (size_t)r * 256 + c * 64 + j * 8;
            cp16f(base + OB_HI + sw, Bhi + gi);
            cp16f(base + OB_LO + sw, Blo + gi);
        }
    };

    load_chunk(0, 0);
    CP_COMMIT();

    const int lrow = lane & 15;
    const int lcol = (lane >> 4) * 8;
    const int cb = wn * 128;

    for (int c = 0; c < 4; c++) {
        int stage = c & 1;
        if (c < 3) { load_chunk(c + 1, stage ^ 1); CP_COMMIT(); CP_WAIT(1); }
        else       { CP_WAIT(0); }
        __syncthreads();
        uint32_t base = sb + stage * STG;

        #pragma unroll
        for (int kk = 0; kk < 4; kk++) {
            uint32_t ah[2][4], al[2][4];
            #pragma unroll
            for (int mt = 0; mt < 2; mt++) {
                uint32_t off = swz((wm * 32 + mt * 16 + lrow) * 128 + (kk * 16 + lcol) * 2);
                ldsm_x4(ah[mt], base + OA_HI + off);
                ldsm_x4(al[mt], base + OA_LO + off);
            }
            #pragma unroll
            for (int ntp = 0; ntp < 8; ntp++) {
                // B addr: q=lane>>3 -> (nt sub, k half)
                int q = lane >> 3;
                int nrow = cb + ntp * 16 + (q >> 1) * 8 + (lane & 7);
                int kcol = kk * 16 + (q & 1) * 8;
                uint32_t boff = swz(nrow * 128 + kcol * 2);
                uint32_t bh[4], bl[4];
                ldsm_x4(bh, base + OB_HI + boff);
                ldsm_x4(bl, base + OB_LO + boff);
                #pragma unroll
                for (int sub = 0; sub < 2; sub++) {
                    int nt = ntp * 2 + sub;
                    #pragma unroll
                    for (int mt = 0; mt < 2; mt++) {
                        mma_bf16(acc[mt][nt], ah[mt], bh + sub * 2);
                        mma_bf16(acc[mt][nt], ah[mt], bl + sub * 2);
                        mma_bf16(acc[mt][nt], al[mt], bh + sub * 2);
                    }
                }
            }
        }
        __syncthreads();
    }

    // ---- epilogue: store C + fused attention coefficients ----
    float sa[4][2], sd[4][2];   // [mt*2+rhalf][head_local]
    #pragma unroll
    for (int i = 0; i < 4; i++) { sa[i][0] = sa[i][1] = 0.f; sd[i][0] = sd[i][1] = 0.f; }

    #pragma unroll
    for (int nt = 0; nt < 16; nt++) {
        int c0 = cb + nt * 8 + (lane & 3) * 2;
        float w0 = __ldg(as + c0), w1 = __ldg(as + c0 + 1);
        float v0 = __ldg(ad + c0), v1 = __ldg(ad + c0 + 1);
        int hl = nt >> 3;
        #pragma unroll
        for (int mt = 0; mt < 2; mt++) {
            sa[mt * 2 + 0][hl] += acc[mt][nt][0] * w0 + acc[mt][nt][1] * w1;
            sa[mt * 2 + 1][hl] += acc[mt][nt][2] * w0 + acc[mt][nt][3] * w1;
            sd[mt * 2 + 0][hl] += acc[mt][nt][0] * v0 + acc[mt][nt][1] * v1;
            sd[mt * 2 + 1][hl] += acc[mt][nt][2] * v0 + acc[mt][nt][3] * v1;
        }
    }
    #pragma unroll
    for (int i = 0; i < 4; i++)
        #pragma unroll
        for (int hl = 0; hl < 2; hl++) {
            sa[i][hl] += __shfl_xor_sync(0xffffffff, sa[i][hl], 1);
            sa[i][hl] += __shfl_xor_sync(0xffffffff, sa[i][hl], 2);
            sd[i][hl] += __shfl_xor_sync(0xffffffff, sd[i][hl], 1);
            sd[i][hl] += __shfl_xor_sync(0xffffffff, sd[i][hl], 2);
        }
    if ((lane & 3) == 0) {
        #pragma unroll
        for (int mt = 0; mt < 2; mt++)
            #pragma unroll
            for (int rh = 0; rh < 2; rh++) {
                int r = row0 + wm * 32 + mt * 16 + (lane >> 2) + rh * 8;
                if (r < M) {
                    #pragma unroll
                    for (int hl = 0; hl < 2; hl++) {
                        g_asrc[r * 4 + wn * 2 + hl] = sa[mt * 2 + rh][hl];
                        g_adst[r * 4 + wn * 2 + hl] = sd[mt * 2 + rh][hl];
                    }
                }
            }
    }

    #pragma unroll
    for (int mt = 0; mt < 2; mt++) {
        int r0 = row0 + wm * 32 + mt * 16 + (lane >> 2);
        int r1 = r0 + 8;
        #pragma unroll
        for (int nt = 0; nt < 16; nt++) {
            int cc = cb + nt * 8 + (lane & 3) * 2;
            if (r0 < M) *(float2*)(C + (size_t)r0 * 256 + cc) = make_float2(acc[mt][nt][0], acc[mt][nt][1]);
            if (r1 < M) *(float2*)(C + (size_t)r1 * 256 + cc) = make_float2(acc[mt][nt][2], acc[mt][nt][3]);
        }
    }
}

// ---------------- fused GAT aggregation + bias + LayerNorm + ReLU ----------------
__global__ void __launch_bounds__(128) k_agg_ln(
    const float* __restrict__ h, const float* __restrict__ bias,
    const float* __restrict__ gamma, const float* __restrict__ beta,
    float* __restrict__ outf, __nv_bfloat16* __restrict__ ohi, __nv_bfloat16* __restrict__ olo)
{
    int n = blockIdx.x;
    int t = threadIdx.x >> 5, lane = threadIdx.x & 31;
    __shared__ float sh[DD];
    __shared__ float red[8];
    int beg = g_rowptr[n], end = g_rowptr[n + 1];
    float adst = g_adst[n * HEADS + t];

    float acc0 = 0.f, acc1 = 0.f, den = 0.f;
    const float* hb = h + t * HIDC;
    int k = beg;
    for (; k + 1 < end; k += 2) {
        int s0 = g_csrsrc[k], s1 = g_csrsrc[k + 1];
        float e0 = g_asrc[s0 * HEADS + t] + adst;
        float e1 = g_asrc[s1 * HEADS + t] + adst;
        e0 = (e0 > 0.f) ? e0 : NEG_SLOPE * e0;
        e1 = (e1 > 0.f) ? e1 : NEG_SLOPE * e1;
        float w0 = __expf(e0), w1 = __expf(e1);
        const float* r0 = hb + (size_t)s0 * DD;
        const float* r1 = hb + (size_t)s1 * DD;
        float a0 = r0[lane], b0 = r0[lane + 32];
        float a1 = r1[lane], b1 = r1[lane + 32];
        den += w0 + w1;
        acc0 = fmaf(w0, a0, fmaf(w1, a1, acc0));
        acc1 = fmaf(w0, b0, fmaf(w1, b1, acc1));
    }
    if (k < end) {
        int s0 = g_csrsrc[k];
        float e0 = g_asrc[s0 * HEADS + t] + adst;
        e0 = (e0 > 0.f) ? e0 : NEG_SLOPE * e0;
        float w0 = __expf(e0);
        const float* r0 = hb + (size_t)s0 * DD;
        den += w0;
        acc0 = fmaf(w0, r0[lane], acc0);
        acc1 = fmaf(w0, r0[lane + 32], acc1);
    }
    float inv = 1.0f / den;
    sh[t * HIDC + lane] = acc0 * inv + bias[t * HIDC + lane];
    sh[t * HIDC + 32 + lane] = acc1 * inv + bias[t * HIDC + 32 + lane];
    __syncthreads();

    float v0 = sh[threadIdx.x], v1 = sh[128 + threadIdx.x];
    float s = v0 + v1;
    #pragma unroll
    for (int off = 16; off > 0; off >>= 1) s += __shfl_xor_sync(0xffffffff, s, off);
    if (lane == 0) red[t] = s;
    __syncthreads();
    float mu = (red[0] + red[1] + red[2] + red[3]) * (1.0f / 256.0f);
    float d0 = v0 - mu, d1 = v1 - mu;
    float q = d0 * d0 + d1 * d1;
    #pragma unroll
    for (int off = 16; off > 0; off >>= 1) q += __shfl_xor_sync(0xffffffff, q, off);
    if (lane == 0) red[4 + t] = q;
    __syncthreads();
    float invs = rsqrtf((red[4] + red[5] + red[6] + red[7]) * (1.0f / 256.0f) + 1e-5f);

    int c0 = threadIdx.x, c1 = 128 + threadIdx.x;
    float y0 = fmaxf(d0 * invs * gamma[c0] + beta[c0], 0.f);
    float y1 = fmaxf(d1 * invs * gamma[c1] + beta[c1], 0.f);
    size_t o = (size_t)n * DD;
    if (outf) {
        outf[o + c0] = y0;
        outf[o + c1] = y1;
    }
    if (ohi) {
        __nv_bfloat16 b0 = __float2bfloat16(y0);
        __nv_bfloat16 b1 = __float2bfloat16(y1);
        ohi[o + c0] = b0; olo[o + c0] = __float2bfloat16(y0 - __bfloat162float(b0));
        ohi[o + c1] = b1; olo[o + c1] = __float2bfloat16(y1 - __bfloat162float(b1));
    }
}

// ---------------- global mean pool ----------------
__global__ void k_pool(const float* __restrict__ h) {
    int g = blockIdx.x;
    int col = blockIdx.y * 128 + threadIdx.x;
    int s = g_gstart[g], e = g_gstart[g + 1];
    float sum = 0.f;
    for (int i = s; i < e; i++) sum += h[(size_t)i * DD + col];
    int cnt = e - s;
    g_pooled[g * DD + col] = sum / (float)max(cnt, 1);
}

// ---------------- final MLP ----------------
__global__ void k_mlp(const float* __restrict__ lw1, const float* __restrict__ lb1,
                      const float* __restrict__ lw2, const float* __restrict__ lb2,
                      float* __restrict__ out) {
    __shared__ float p[DD];
    __shared__ float hid[HIDC];
    int g = blockIdx.x, tid = threadIdx.x;
    for (int i = tid; i < DD; i += 64) p[i] = g_pooled[g * DD + i];
    __syncthreads();
    float s = lb1[tid];
    #pragma unroll 8
    for (int k = 0; k < DD; k++) s = fmaf(p[k], lw1[k * HIDC + tid], s);
    hid[tid] = fmaxf(s, 0.f);
    __syncthreads();
    if (tid < 2) {
        float o = lb2[tid];
        #pragma unroll
        for (int k = 0; k < HIDC; k++) o = fmaf(hid[k], lw2[k * 2 + tid], o);
        out[g * 2 + tid] = o;
    }
}

// ---------------- host launcher ----------------
extern "C" void kernel_launch(void* const* d_in, const int* in_sizes, int n_in,
                              void* d_out, int out_size) {
    const float* x   = (const float*)d_in[0];
    const int*   ei  = (const int*)d_in[1];
    const int*   bat = (const int*)d_in[2];
    const float* W1  = (const float*)d_in[3];
    const float* as1 = (const float*)d_in[4];
    const float* ad1 = (const float*)d_in[5];
    const float* b1  = (const float*)d_in[6];
    const float* g1  = (const float*)d_in[7];
    const float* be1 = (const float*)d_in[8];
    const float* W2  = (const float*)d_in[9];
    const float* as2 = (const float*)d_in[10];
    const float* ad2 = (const float*)d_in[11];
    const float* b2  = (const float*)d_in[12];
    const float* g2  = (const float*)d_in[13];
    const float* be2 = (const float*)d_in[14];
    const float* lw1 = (const float*)d_in[15];
    const float* lb1 = (const float*)d_in[16];
    const float* lw2 = (const float*)d_in[17];
    const float* lb2 = (const float*)d_in[18];
    float* out = (float*)d_out;

    cudaFuncSetAttribute(k_gemm_att, cudaFuncAttributeMaxDynamicSharedMemorySize, SMEM_TOT);

    float *bh, *bo;
    __nv_bfloat16 *ahi, *alo, *w1h, *w1l, *w2h, *w2l;
    cudaGetSymbolAddress((void**)&bh, g_h);
    cudaGetSymbolAddress((void**)&bo, g_o);
    cudaGetSymbolAddress((void**)&ahi, g_ahi);
    cudaGetSymbolAddress((void**)&alo, g_alo);
    cudaGetSymbolAddress((void**)&w1h, g_w1hi);
    cudaGetSymbolAddress((void**)&w1l, g_w1lo);
    cudaGetSymbolAddress((void**)&w2h, g_w2hi);
    cudaGetSymbolAddress((void**)&w2l, g_w2lo);

    // CSR + batch ranges + splits
    k_zero_counts<<<(NN + 255) / 256, 256>>>();
    k_hist_edges<<<(ETOT + 255) / 256, 256>>>(ei);
    k_hist_batch<<<(NN + 255) / 256, 256>>>(bat);
    k_scan_part<<<SNB, 512>>>();
    k_scan_boff<<<1, 1>>>();
    k_scan_add<<<(NN + 255) / 256, 256>>>();
    k_scatter_edges<<<(ETOT + 255) / 256, 256>>>(ei);
    k_scan_batch<<<1, 1>>>();
    k_split_x<<<NN * DD / 256, 256>>>(x, ahi, alo);
    k_split_wt<<<DD * DD / 256, 256>>>(W1, w1h, w1l);
    k_split_wt<<<DD * DD / 256, 256>>>(W2, w2h, w2l);

    int gemm_blocks = (NN + 127) / 128;

    // ---- layer 1 ----
    k_gemm_att<<<gemm_blocks, 256, SMEM_TOT>>>(ahi, alo, w1h, w1l, bh, as1, ad1, NN);
    k_agg_ln<<<NN, 128>>>(bh, b1, g1, be1, nullptr, ahi, alo);

    // ---- layer 2 ----
    k_gemm_att<<<gemm_blocks, 256, SMEM_TOT>>>(ahi, alo, w2h, w2l, bh, as2, ad2, NN);
    k_agg_ln<<<NN, 128>>>(bh, b2, g2, be2, bo, nullptr, nullptr);

    // ---- pool + MLP ----
    k_pool<<<dim3(GG, 2), 128>>>(bo);
    k_mlp<<<GG, 64>>>(lw1, lb1, lw2, lb2, out);
}

// round 5
// speedup vs baseline: 1.6933x; 1.0374x over previous
#include <cuda_runtime.h>
#include <cuda_bf16.h>
#include <cstdint>
#include <math.h>

#define NN 50000
#define EE 400000
#define ETOT (EE + NN)
#define DD 256
#define HEADS 4
#define HIDC 64
#define GG 64
#define NEG_SLOPE 0.2f

// ---------------- static device scratch ----------------
__device__ __nv_bfloat162 g_hb[NN * 128];   // GEMM output h as bf16 pairs
__device__ float g_o[NN * DD];              // post agg+LN features (layer 2, fp32 for pooling)
__device__ __nv_bfloat16 g_ahi[NN * DD];
__device__ __nv_bfloat16 g_alo[NN * DD];
__device__ __nv_bfloat16 g_w1hi[DD * DD], g_w1lo[DD * DD];
__device__ __nv_bfloat16 g_w2hi[DD * DD], g_w2lo[DD * DD];
__device__ float g_asrc[NN * HEADS];
__device__ float g_adst[NN * HEADS];
__device__ int   g_deg[NN];
__device__ int   g_rowptr[NN + 1];
__device__ int   g_cursor[NN];
__device__ int   g_csrsrc[ETOT];
__device__ int   g_gcnt[GG];
__device__ int   g_gstart[GG + 1];
__device__ float g_pooled[GG * DD];
#define SNB 98
__device__ int   g_bsum[SNB];
__device__ int   g_boff[SNB];

// ---------------- helpers ----------------
__device__ __forceinline__ uint32_t su32(const void* p) {
    uint32_t a;
    asm("{ .reg .u64 t; cvta.to.shared.u64 t, %1; cvt.u32.u64 %0, t; }" : "=r"(a) : "l"(p));
    return a;
}
__device__ __forceinline__ uint32_t swz(uint32_t off) {
    return off ^ ((off >> 3) & 0x70);
}
__device__ __forceinline__ void ldsm_x4(uint32_t* r, uint32_t addr) {
    asm volatile("ldmatrix.sync.aligned.m8n8.x4.shared.b16 {%0,%1,%2,%3}, [%4];"
                 : "=r"(r[0]), "=r"(r[1]), "=r"(r[2]), "=r"(r[3]) : "r"(addr));
}
__device__ __forceinline__ void mma_bf16(float* c, const uint32_t* a, const uint32_t* b) {
    asm volatile("mma.sync.aligned.m16n8k16.row.col.f32.bf16.bf16.f32 "
                 "{%0,%1,%2,%3}, {%4,%5,%6,%7}, {%8,%9}, {%0,%1,%2,%3};"
                 : "+f"(c[0]), "+f"(c[1]), "+f"(c[2]), "+f"(c[3])
                 : "r"(a[0]), "r"(a[1]), "r"(a[2]), "r"(a[3]), "r"(b[0]), "r"(b[1]));
}
__device__ __forceinline__ void cp16(uint32_t dst, const void* src, uint32_t sz) {
    asm volatile("cp.async.cg.shared.global [%0], [%1], 16, %2;" :: "r"(dst), "l"(src), "r"(sz));
}
__device__ __forceinline__ void cp16f(uint32_t dst, const void* src) {
    asm volatile("cp.async.cg.shared.global [%0], [%1], 16;" :: "r"(dst), "l"(src));
}
#define CP_COMMIT() asm volatile("cp.async.commit_group;" ::: "memory")
#define CP_WAIT(n)  asm volatile("cp.async.wait_group %0;" :: "n"(n) : "memory")

// ---------------- CSR build ----------------
__global__ void k_zero_counts() {
    int i = blockIdx.x * blockDim.x + threadIdx.x;
    if (i < NN) g_deg[i] = 0;
    if (i < GG) g_gcnt[i] = 0;
}
__global__ void k_hist_edges(const int* __restrict__ ei) {
    int i = blockIdx.x * blockDim.x + threadIdx.x;
    if (i < EE) atomicAdd(&g_deg[ei[EE + i]], 1);
    else if (i < ETOT) atomicAdd(&g_deg[i - EE], 1);
}
__global__ void k_scan_part() {
    __shared__ int sh[512];
    int i = blockIdx.x * 512 + threadIdx.x;
    int v = (i < NN) ? g_deg[i] : 0;
    sh[threadIdx.x] = v;
    __syncthreads();
    #pragma unroll
    for (int off = 1; off < 512; off <<= 1) {
        int t = (threadIdx.x >= off) ? sh[threadIdx.x - off] : 0;
        __syncthreads();
        sh[threadIdx.x] += t;
        __syncthreads();
    }
    if (i < NN) g_rowptr[i] = sh[threadIdx.x] - v;
    if (threadIdx.x == 511) g_bsum[blockIdx.x] = sh[511];
}
__global__ void k_scan_boff() {
    int c = 0;
    for (int b = 0; b < SNB; b++) { g_boff[b] = c; c += g_bsum[b]; }
}
__global__ void k_scan_add() {
    int i = blockIdx.x * blockDim.x + threadIdx.x;
    if (i < NN) {
        int val = g_rowptr[i] + g_boff[i >> 9];
        g_rowptr[i] = val;
        g_cursor[i] = val;
    }
    if (i == 0) g_rowptr[NN] = ETOT;
}
__global__ void k_scatter_edges(const int* __restrict__ ei) {
    int i = blockIdx.x * blockDim.x + threadIdx.x;
    int src, dst;
    if (i < EE)        { src = ei[i]; dst = ei[EE + i]; }
    else if (i < ETOT) { src = i - EE; dst = i - EE; }
    else return;
    int pos = atomicAdd(&g_cursor[dst], 1);
    g_csrsrc[pos] = src;
}
__global__ void k_hist_batch(const int* __restrict__ batch) {
    int i = blockIdx.x * blockDim.x + threadIdx.x;
    if (i < NN) atomicAdd(&g_gcnt[batch[i]], 1);
}
__global__ void k_scan_batch() {
    int c = 0;
    for (int g = 0; g < GG; g++) { g_gstart[g] = c; c += g_gcnt[g]; }
    g_gstart[GG] = c;
}

// ---------------- fp32 -> bf16 hi/lo splits ----------------
__global__ void k_split_x(const float* __restrict__ x,
                          __nv_bfloat16* __restrict__ hi, __nv_bfloat16* __restrict__ lo) {
    int i = blockIdx.x * 256 + threadIdx.x;
    float v = x[i];
    __nv_bfloat16 h = __float2bfloat16(v);
    hi[i] = h;
    lo[i] = __float2bfloat16(v - __bfloat162float(h));
}
__global__ void k_split_wt(const float* __restrict__ W,
                           __nv_bfloat16* __restrict__ hi, __nv_bfloat16* __restrict__ lo) {
    int i = blockIdx.x * 256 + threadIdx.x;
    int n = i >> 8, k = i & 255;
    float v = W[k * 256 + n];
    __nv_bfloat16 h = __float2bfloat16(v);
    hi[i] = h;
    lo[i] = __float2bfloat16(v - __bfloat162float(h));
}

// ---------------- GEMM: h[M,256] = A @ Wt^T  (bf16 out) + fused att-coef epilogue ----------------
#define STG   98304
#define OA_HI 0
#define OA_LO 16384
#define OB_HI 32768
#define OB_LO 65536
#define SMEM_TOT (2 * STG)

__global__ void __launch_bounds__(256) k_gemm_att(
    const __nv_bfloat16* __restrict__ Ahi, const __nv_bfloat16* __restrict__ Alo,
    const __nv_bfloat16* __restrict__ Bhi, const __nv_bfloat16* __restrict__ Blo,
    __nv_bfloat162* __restrict__ Hout,
    const float* __restrict__ as, const float* __restrict__ ad,
    int M)
{
    extern __shared__ char smem[];
    uint32_t sb = su32(smem);
    const int tid = threadIdx.x, wid = tid >> 5, lane = tid & 31;
    const int row0 = blockIdx.x * 128;
    const int wm = wid & 3;
    const int wn = wid >> 2;

    float acc[2][16][4];
    #pragma unroll
    for (int a = 0; a < 2; a++)
        #pragma unroll
        for (int b = 0; b < 16; b++)
            #pragma unroll
            for (int q = 0; q < 4; q++) acc[a][b][q] = 0.f;

    auto load_chunk = [&](int c, int stage) {
        uint32_t base = sb + stage * STG;
        #pragma unroll
        for (int it = 0; it < 4; it++) {
            int u = tid + it * 256;
            int r = u >> 3, j = u & 7;
            uint32_t sw = swz(r * 128 + j * 16);
            int m = row0 + r;
            int mc = m < M ? m : (M - 1);
            uint32_t sz = (m < M) ? 16u : 0u;
            size_t gi = (size_t)mc * 256 + c * 64 + j * 8;
            cp16(base + OA_HI + sw, Ahi + gi, sz);
            cp16(base + OA_LO + sw, Alo + gi, sz);
        }
        #pragma unroll
        for (int it = 0; it < 8; it++) {
            int u = tid + it * 256;
            int r = u >> 3, j = u & 7;
            uint32_t sw = swz(r * 128 + j * 16);
            size_t gi = (size_t)r * 256 + c * 64 + j * 8;
            cp16f(base + OB_HI + sw, Bhi + gi);
            cp16f(base + OB_LO + sw, Blo + gi);
        }
    };

    load_chunk(0, 0);
    CP_COMMIT();

    const int lrow = lane & 15;
    const int lcol = (lane >> 4) * 8;
    const int cb = wn * 128;

    for (int c = 0; c < 4; c++) {
        int stage = c & 1;
        if (c < 3) { load_chunk(c + 1, stage ^ 1); CP_COMMIT(); CP_WAIT(1); }
        else       { CP_WAIT(0); }
        __syncthreads();
        uint32_t base = sb + stage * STG;

        #pragma unroll
        for (int kk = 0; kk < 4; kk++) {
            uint32_t ah[2][4], al[2][4];
            #pragma unroll
            for (int mt = 0; mt < 2; mt++) {
                uint32_t off = swz((wm * 32 + mt * 16 + lrow) * 128 + (kk * 16 + lcol) * 2);
                ldsm_x4(ah[mt], base + OA_HI + off);
                ldsm_x4(al[mt], base + OA_LO + off);
            }
            #pragma unroll
            for (int ntp = 0; ntp < 8; ntp++) {
                int q = lane >> 3;
                int nrow = cb + ntp * 16 + (q >> 1) * 8 + (lane & 7);
                int kcol = kk * 16 + (q & 1) * 8;
                uint32_t boff = swz(nrow * 128 + kcol * 2);
                uint32_t bh[4], bl[4];
                ldsm_x4(bh, base + OB_HI + boff);
                ldsm_x4(bl, base + OB_LO + boff);
                #pragma unroll
                for (int sub = 0; sub < 2; sub++) {
                    int nt = ntp * 2 + sub;
                    #pragma unroll
                    for (int mt = 0; mt < 2; mt++) {
                        mma_bf16(acc[mt][nt], ah[mt], bh + sub * 2);
                        mma_bf16(acc[mt][nt], ah[mt], bl + sub * 2);
                        mma_bf16(acc[mt][nt], al[mt], bh + sub * 2);
                    }
                }
            }
        }
        __syncthreads();
    }

    // ---- epilogue: attention coefficients (fp32) + bf16 h store ----
    float sa[4][2], sd[4][2];
    #pragma unroll
    for (int i = 0; i < 4; i++) { sa[i][0] = sa[i][1] = 0.f; sd[i][0] = sd[i][1] = 0.f; }

    #pragma unroll
    for (int nt = 0; nt < 16; nt++) {
        int c0 = cb + nt * 8 + (lane & 3) * 2;
        float w0 = __ldg(as + c0), w1 = __ldg(as + c0 + 1);
        float v0 = __ldg(ad + c0), v1 = __ldg(ad + c0 + 1);
        int hl = nt >> 3;
        #pragma unroll
        for (int mt = 0; mt < 2; mt++) {
            sa[mt * 2 + 0][hl] += acc[mt][nt][0] * w0 + acc[mt][nt][1] * w1;
            sa[mt * 2 + 1][hl] += acc[mt][nt][2] * w0 + acc[mt][nt][3] * w1;
            sd[mt * 2 + 0][hl] += acc[mt][nt][0] * v0 + acc[mt][nt][1] * v1;
            sd[mt * 2 + 1][hl] += acc[mt][nt][2] * v0 + acc[mt][nt][3] * v1;
        }
    }
    #pragma unroll
    for (int i = 0; i < 4; i++)
        #pragma unroll
        for (int hl = 0; hl < 2; hl++) {
            sa[i][hl] += __shfl_xor_sync(0xffffffff, sa[i][hl], 1);
            sa[i][hl] += __shfl_xor_sync(0xffffffff, sa[i][hl], 2);
            sd[i][hl] += __shfl_xor_sync(0xffffffff, sd[i][hl], 1);
            sd[i][hl] += __shfl_xor_sync(0xffffffff, sd[i][hl], 2);
        }
    if ((lane & 3) == 0) {
        #pragma unroll
        for (int mt = 0; mt < 2; mt++)
            #pragma unroll
            for (int rh = 0; rh < 2; rh++) {
                int r = row0 + wm * 32 + mt * 16 + (lane >> 2) + rh * 8;
                if (r < M) {
                    #pragma unroll
                    for (int hl = 0; hl < 2; hl++) {
                        g_asrc[r * 4 + wn * 2 + hl] = sa[mt * 2 + rh][hl];
                        g_adst[r * 4 + wn * 2 + hl] = sd[mt * 2 + rh][hl];
                    }
                }
            }
    }

    #pragma unroll
    for (int mt = 0; mt < 2; mt++) {
        int r0 = row0 + wm * 32 + mt * 16 + (lane >> 2);
        int r1 = r0 + 8;
        #pragma unroll
        for (int nt = 0; nt < 16; nt++) {
            int cc2 = (cb >> 1) + nt * 4 + (lane & 3);   // bf16x2 index
            if (r0 < M) Hout[(size_t)r0 * 128 + cc2] = __floats2bfloat162_rn(acc[mt][nt][0], acc[mt][nt][1]);
            if (r1 < M) Hout[(size_t)r1 * 128 + cc2] = __floats2bfloat162_rn(acc[mt][nt][2], acc[mt][nt][3]);
        }
    }
}

// ---------------- fused GAT aggregation (bf16 gather) + bias + LayerNorm + ReLU ----------------
__global__ void __launch_bounds__(128) k_agg_ln(
    const __nv_bfloat162* __restrict__ hb, const float* __restrict__ bias,
    const float* __restrict__ gamma, const float* __restrict__ beta,
    float* __restrict__ outf, __nv_bfloat162* __restrict__ ohi, __nv_bfloat162* __restrict__ olo)
{
    int n = blockIdx.x;
    int t = threadIdx.x >> 5, lane = threadIdx.x & 31;
    __shared__ float red[8];
    int beg = g_rowptr[n], end = g_rowptr[n + 1];
    float adst = g_adst[n * HEADS + t];

    float acc0 = 0.f, acc1 = 0.f, den = 0.f;
    const __nv_bfloat162* hp = hb + t * 32 + lane;   // this lane's channel pair within head t
    int k = beg;
    for (; k + 1 < end; k += 2) {
        int s0 = g_csrsrc[k], s1 = g_csrsrc[k + 1];
        __nv_bfloat162 v0 = hp[(size_t)s0 * 128];
        __nv_bfloat162 v1 = hp[(size_t)s1 * 128];
        float e0 = g_asrc[s0 * HEADS + t] + adst;
        float e1 = g_asrc[s1 * HEADS + t] + adst;
        e0 = (e0 > 0.f) ? e0 : NEG_SLOPE * e0;
        e1 = (e1 > 0.f) ? e1 : NEG_SLOPE * e1;
        float w0 = __expf(e0), w1 = __expf(e1);
        float2 f0 = __bfloat1622float2(v0);
        float2 f1 = __bfloat1622float2(v1);
        den += w0 + w1;
        acc0 = fmaf(w0, f0.x, fmaf(w1, f1.x, acc0));
        acc1 = fmaf(w0, f0.y, fmaf(w1, f1.y, acc1));
    }
    if (k < end) {
        int s0 = g_csrsrc[k];
        __nv_bfloat162 v0 = hp[(size_t)s0 * 128];
        float e0 = g_asrc[s0 * HEADS + t] + adst;
        e0 = (e0 > 0.f) ? e0 : NEG_SLOPE * e0;
        float w0 = __expf(e0);
        float2 f0 = __bfloat1622float2(v0);
        den += w0;
        acc0 = fmaf(w0, f0.x, acc0);
        acc1 = fmaf(w0, f0.y, acc1);
    }
    float inv = 1.0f / den;
    int c0 = 2 * threadIdx.x, c1 = c0 + 1;
    float m0 = acc0 * inv + bias[c0];
    float m1 = acc1 * inv + bias[c1];

    // block LayerNorm over 256 channels (each thread owns channels c0, c1)
    float s = m0 + m1;
    #pragma unroll
    for (int off = 16; off > 0; off >>= 1) s += __shfl_xor_sync(0xffffffff, s, off);
    if (lane == 0) red[t] = s;
    __syncthreads();
    float mu = (red[0] + red[1] + red[2] + red[3]) * (1.0f / 256.0f);
    float d0 = m0 - mu, d1 = m1 - mu;
    float q = d0 * d0 + d1 * d1;
    #pragma unroll
    for (int off = 16; off > 0; off >>= 1) q += __shfl_xor_sync(0xffffffff, q, off);
    if (lane == 0) red[4 + t] = q;
    __syncthreads();
    float invs = rsqrtf((red[4] + red[5] + red[6] + red[7]) * (1.0f / 256.0f) + 1e-5f);

    float y0 = fmaxf(d0 * invs * gamma[c0] + beta[c0], 0.f);
    float y1 = fmaxf(d1 * invs * gamma[c1] + beta[c1], 0.f);
    size_t o = (size_t)n * 128 + threadIdx.x;
    if (outf) {
        *(float2*)(outf + 2 * o) = make_float2(y0, y1);
    }
    if (ohi) {
        __nv_bfloat16 h0 = __float2bfloat16(y0);
        __nv_bfloat16 h1 = __float2bfloat16(y1);
        ohi[o] = __nv_bfloat162(h0, h1);
        olo[o] = __nv_bfloat162(__float2bfloat16(y0 - __bfloat162float(h0)),
                                __float2bfloat16(y1 - __bfloat162float(h1)));
    }
}

// ---------------- global mean pool ----------------
__global__ void k_pool(const float* __restrict__ h) {
    int g = blockIdx.x;
    int col = blockIdx.y * 128 + threadIdx.x;
    int s = g_gstart[g], e = g_gstart[g + 1];
    float sum = 0.f;
    for (int i = s; i < e; i++) sum += h[(size_t)i * DD + col];
    int cnt = e - s;
    g_pooled[g * DD + col] = sum / (float)max(cnt, 1);
}

// ---------------- final MLP ----------------
__global__ void k_mlp(const float* __restrict__ lw1, const float* __restrict__ lb1,
                      const float* __restrict__ lw2, const float* __restrict__ lb2,
                      float* __restrict__ out) {
    __shared__ float p[DD];
    __shared__ float hid[HIDC];
    int g = blockIdx.x, tid = threadIdx.x;
    for (int i = tid; i < DD; i += 64) p[i] = g_pooled[g * DD + i];
    __syncthreads();
    float s = lb1[tid];
    #pragma unroll 8
    for (int k = 0; k < DD; k++) s = fmaf(p[k], lw1[k * HIDC + tid], s);
    hid[tid] = fmaxf(s, 0.f);
    __syncthreads();
    if (tid < 2) {
        float o = lb2[tid];
        #pragma unroll
        for (int k = 0; k < HIDC; k++) o = fmaf(hid[k], lw2[k * 2 + tid], o);
        out[g * 2 + tid] = o;
    }
}

// ---------------- host launcher ----------------
extern "C" void kernel_launch(void* const* d_in, const int* in_sizes, int n_in,
                              void* d_out, int out_size) {
    const float* x   = (const float*)d_in[0];
    const int*   ei  = (const int*)d_in[1];
    const int*   bat = (const int*)d_in[2];
    const float* W1  = (const float*)d_in[3];
    const float* as1 = (const float*)d_in[4];
    const float* ad1 = (const float*)d_in[5];
    const float* b1  = (const float*)d_in[6];
    const float* g1  = (const float*)d_in[7];
    const float* be1 = (const float*)d_in[8];
    const float* W2  = (const float*)d_in[9];
    const float* as2 = (const float*)d_in[10];
    const float* ad2 = (const float*)d_in[11];
    const float* b2  = (const float*)d_in[12];
    const float* g2  = (const float*)d_in[13];
    const float* be2 = (const float*)d_in[14];
    const float* lw1 = (const float*)d_in[15];
    const float* lb1 = (const float*)d_in[16];
    const float* lw2 = (const float*)d_in[17];
    const float* lb2 = (const float*)d_in[18];
    float* out = (float*)d_out;

    cudaFuncSetAttribute(k_gemm_att, cudaFuncAttributeMaxDynamicSharedMemorySize, SMEM_TOT);

    float *bo;
    __nv_bfloat162 *hb;
    __nv_bfloat16 *ahi, *alo, *w1h, *w1l, *w2h, *w2l;
    cudaGetSymbolAddress((void**)&hb, g_hb);
    cudaGetSymbolAddress((void**)&bo, g_o);
    cudaGetSymbolAddress((void**)&ahi, g_ahi);
    cudaGetSymbolAddress((void**)&alo, g_alo);
    cudaGetSymbolAddress((void**)&w1h, g_w1hi);
    cudaGetSymbolAddress((void**)&w1l, g_w1lo);
    cudaGetSymbolAddress((void**)&w2h, g_w2hi);
    cudaGetSymbolAddress((void**)&w2l, g_w2lo);

    // CSR + batch ranges + splits
    k_zero_counts<<<(NN + 255) / 256, 256>>>();
    k_hist_edges<<<(ETOT + 255) / 256, 256>>>(ei);
    k_hist_batch<<<(NN + 255) / 256, 256>>>(bat);
    k_scan_part<<<SNB, 512>>>();
    k_scan_boff<<<1, 1>>>();
    k_scan_add<<<(NN + 255) / 256, 256>>>();
    k_scatter_edges<<<(ETOT + 255) / 256, 256>>>(ei);
    k_scan_batch<<<1, 1>>>();
    k_split_x<<<NN * DD / 256, 256>>>(x, ahi, alo);
    k_split_wt<<<DD * DD / 256, 256>>>(W1, w1h, w1l);
    k_split_wt<<<DD * DD / 256, 256>>>(W2, w2h, w2l);

    int gemm_blocks = (NN + 127) / 128;

    // ---- layer 1 ----
    k_gemm_att<<<gemm_blocks, 256, SMEM_TOT>>>(ahi, alo, w1h, w1l, hb, as1, ad1, NN);
    k_agg_ln<<<NN, 128>>>(hb, b1, g1, be1, nullptr, (__nv_bfloat162*)ahi, (__nv_bfloat162*)alo);

    // ---- layer 2 ----
    k_gemm_att<<<gemm_blocks, 256, SMEM_TOT>>>(ahi, alo, w2h, w2l, hb, as2, ad2, NN);
    k_agg_ln<<<NN, 128>>>(hb, b2, g2, be2, bo, nullptr, nullptr);

    // ---- pool + MLP ----
    k_pool<<<dim3(GG, 2), 128>>>(bo);
    k_mlp<<<GG, 64>>>(lw1, lb1, lw2, lb2, out);
}